// round 10
// baseline (speedup 1.0000x reference)
#include <cuda_runtime.h>
#include <cuda_fp16.h>
#include <math.h>

#define N_NODES 20000
#define N_EDGES 320000
#define CAP     96      // bucket capacity per node (Poisson(16); P(deg>=96) ~ 1e-60)

__device__ float  g_M0[96 * 64];
__device__ float  g_M1[96 * 32];
// fp16 precompute, interleaved: per node 384 halves (768B):
//   [0,256):  group c (c<64) at 4c:   {R[c], U0[c], U1[c], U2[c]}
//   [256,384): group w (w<32) at 256+4w: {P[w], Q0[w], Q1[w], Q2[w]}
__device__ __half g_preh[(size_t)N_NODES * 384];   // ~15.4 MB
__device__ int    g_cursor[N_NODES];   // zero at load; re-zeroed by gather_ln each launch
__device__ int    g_psrc[(size_t)N_NODES * CAP];
__device__ float4 g_pattr[(size_t)N_NODES * CAP];

// ---------------------------------------------------------------------------
// Launch 1: M-build (4-way k-split + quad shuffle) overlapped with scatter.
// Threads [0, 36864) build M0/M1; threads beyond scatter edges (no smem).
// Scatter relies on cursors being zero: true at load (static zero-init) and
// after every gather_ln (which resets them). CAP clamp makes any violation
// non-corrupting.
// ---------------------------------------------------------------------------
#define MB_THREADS (4 * 9216)   // 36864, multiple of 256
__global__ void init_scatter(const float* __restrict__ W0, const float* __restrict__ W1,
                             const float* __restrict__ V0, const float* __restrict__ V1,
                             const int* __restrict__ ei, const float* __restrict__ ea) {
    int t = blockIdx.x * blockDim.x + threadIdx.x;
    if (t < 4 * 6144) {                    // M0: 6144 outputs x 4 lanes
        int out = t >> 2, l4 = t & 3;
        int u = out >> 6, c = out & 63;
        float acc = 0.f;
        int k0 = l4 * 32;
        #pragma unroll
        for (int kk = 0; kk < 32; ++kk)
            acc += W0[u * 128 + k0 + kk] * V0[(k0 + kk) * 64 + c];
        acc += __shfl_xor_sync(0xFFFFFFFFu, acc, 1);
        acc += __shfl_xor_sync(0xFFFFFFFFu, acc, 2);
        if (l4 == 0) {
            float s = 1.0f / sqrtf(96.0f * 128.0f);
            if (u >= 64) s *= 0.5773502691896258f;   // fold 1/sqrt(3)
            g_M0[out] = acc * s;
        }
    } else if (t < MB_THREADS) {           // M1: 3072 outputs x 4 lanes
        int t2 = t - 4 * 6144;
        int out = t2 >> 2, l4 = t2 & 3;
        int u = out >> 5, w = out & 31;
        float acc = 0.f;
        int k0 = l4 * 16;
        #pragma unroll
        for (int kk = 0; kk < 16; ++kk)
            acc += W1[u * 64 + k0 + kk] * V1[(k0 + kk) * 32 + w];
        acc += __shfl_xor_sync(0xFFFFFFFFu, acc, 1);
        acc += __shfl_xor_sync(0xFFFFFFFFu, acc, 2);
        if (l4 == 0) g_M1[out] = acc * (1.0f / sqrtf(96.0f * 64.0f));
    } else {                               // scatter
        int e = t - MB_THREADS;
        if (e < N_EDGES) {
            int src = ei[e];
            int dst = ei[N_EDGES + e];
            float4 a = ((const float4*)ea)[e];
            int pos = atomicAdd(&g_cursor[dst], 1);
            if (pos < CAP) {               // hard safety clamp: no OOB ever
                size_t idx = (size_t)dst * CAP + pos;
                g_psrc[idx]  = src;
                g_pattr[idx] = a;
            }
        }
    }
}

// ---------------------------------------------------------------------------
// accum: 4 output cols (m) x 4 nodes (f). acc[nn] += m * f[nn].
// ---------------------------------------------------------------------------
template <int ITERS>
__device__ __forceinline__ void accum4x4(const float* __restrict__ mbase, int mstride,
                                         const float* __restrict__ fbase, int fstride,
                                         float4 acc[4]) {
    #pragma unroll 8
    for (int u = 0; u < ITERS; ++u) {
        float4 m = *(const float4*)(mbase + u * mstride);
        float4 f = *(const float4*)(fbase + u * fstride);
        acc[0].x += m.x * f.x; acc[0].y += m.y * f.x; acc[0].z += m.z * f.x; acc[0].w += m.w * f.x;
        acc[1].x += m.x * f.y; acc[1].y += m.y * f.y; acc[1].z += m.z * f.y; acc[1].w += m.w * f.y;
        acc[2].x += m.x * f.z; acc[2].y += m.y * f.z; acc[2].z += m.z * f.z; acc[2].w += m.w * f.z;
        acc[3].x += m.x * f.w; acc[3].y += m.y * f.w; acc[3].z += m.z * f.w; acc[3].w += m.w * f.w;
    }
}

// ---------------------------------------------------------------------------
// Launch 2: node_pre only (16 nodes/block, register-tiled 4x4).
// ---------------------------------------------------------------------------
#define NPB 16
#define PRE_BLOCKS (N_NODES / NPB)                   // 1250

__global__ __launch_bounds__(384) void node_pre(const float* __restrict__ nf) {
    __shared__ float sM0[96 * 64];      // 24 KB
    __shared__ float sM1[96 * 32];      // 12 KB
    __shared__ float sfT[160 * 16];     // 10 KB: transposed features [ch][node]
    int t = threadIdx.x;
    int n0 = blockIdx.x * NPB;
    for (int i = t; i < 96 * 64; i += 384) sM0[i] = g_M0[i];
    for (int i = t; i < 96 * 32; i += 384) sM1[i] = g_M1[i];
    for (int i = t; i < 16 * 160; i += 384) {
        int n = i / 160, ch = i - n * 160;
        sfT[ch * 16 + n] = nf[(size_t)(n0 + n) * 160 + ch];
    }
    __syncthreads();

    float4 acc[4] = {{0,0,0,0},{0,0,0,0},{0,0,0,0},{0,0,0,0}};
    int g, pbase;

    if (t < 64) {                                  // R
        int h = t & 15; g = t >> 4;
        pbase = 16 * h;
        accum4x4<64>(sM0 + 4 * h, 64, sfT + 4 * g, 16, acc);
    } else if (t < 256) {                          // U_i
        int idx = t - 64;
        g = idx / 48; int r = idx % 48, i = r >> 4, cc = r & 15;
        pbase = 16 * cc + 1 + i;
        accum4x4<32>(sM0 + 64 * 64 + 4 * cc, 64, sfT + (64 + i) * 16 + 4 * g, 48, acc);
    } else if (t < 288) {                          // P
        int idx = t - 256;
        g = idx >> 3; int r = idx & 7;
        pbase = 256 + 16 * r;
        accum4x4<64>(sM1 + 4 * r, 32, sfT + 4 * g, 16, acc);
    } else {                                       // Q_i
        int idx = t - 288;
        g = idx / 24; int r = idx % 24, i = r >> 3, ww = r & 7;
        pbase = 256 + 16 * ww + 1 + i;
        accum4x4<32>(sM1 + 64 * 32 + 4 * ww, 32, sfT + (64 + i) * 16 + 4 * g, 48, acc);
    }

    size_t outb = (size_t)(n0 + 4 * g) * 384 + pbase;
    #pragma unroll
    for (int nn = 0; nn < 4; ++nn) {
        __half* o = g_preh + outb + (size_t)nn * 384;
        o[0]  = __float2half_rn(acc[nn].x);
        o[4]  = __float2half_rn(acc[nn].y);
        o[8]  = __float2half_rn(acc[nn].z);
        o[12] = __float2half_rn(acc[nn].w);
    }
}

// ---------------------------------------------------------------------------
// Launch 3: gather + fused LayerNorm, 2 warps per node (edges split by parity),
// partials merged via smem; resets g_cursor for the next launch.
// Block = 256 thr = 4 nodes x 64 thr. Grid = 5000 (exact).
// ---------------------------------------------------------------------------
__global__ __launch_bounds__(256) void gather_ln(float* __restrict__ out,
                                                 const float* __restrict__ gamma,
                                                 const float* __restrict__ beta) {
    __shared__ float spart[4][160];
    int slot = threadIdx.x >> 6;            // node slot in block, 0..3
    int node = blockIdx.x * 4 + slot;
    int wid2 = (threadIdx.x >> 5) & 1;      // which half-warp-pair
    int lane = threadIdx.x & 31;
    int cnt = g_cursor[node];
    cnt = cnt < CAP ? cnt : CAP;
    const int*    psrc  = g_psrc  + (size_t)node * CAP;
    const float4* pattr = g_pattr + (size_t)node * CAP;

    float ax = 0.f, ay = 0.f, c0 = 0.f, c1 = 0.f, c2 = 0.f;

    for (int b = wid2; b < cnt; b += 2) {
        int    src = __ldg(&psrc[b]);      // uniform broadcast
        float4 A   = __ldg(&pattr[b]);     // uniform broadcast
        float e0 = A.x, ex = A.y, ey = A.z, ez = A.w;
        const __half* pb = g_preh + (size_t)src * 384;
        uint4 bg = *(const uint4*)(pb + 8 * lane);        // groups 2l, 2l+1
        uint2 sm = *(const uint2*)(pb + 256 + 4 * lane);  // group l (small)
        float2 p0 = __half22float2(*(__half2*)&bg.x);     // R(2l),  U0(2l)
        float2 p1 = __half22float2(*(__half2*)&bg.y);     // U1(2l), U2(2l)
        float2 p2 = __half22float2(*(__half2*)&bg.z);     // R(2l+1),U0(2l+1)
        float2 p3 = __half22float2(*(__half2*)&bg.w);     // U1,U2 (2l+1)
        float2 s0 = __half22float2(*(__half2*)&sm.x);     // P(l), Q0(l)
        float2 s1 = __half22float2(*(__half2*)&sm.y);     // Q1(l), Q2(l)
        ax += e0 * p0.x + ex * p0.y + ey * p1.x + ez * p1.y;
        ay += e0 * p2.x + ex * p2.y + ey * p3.x + ez * p3.y;
        c0 += ex * s0.x + e0 * s0.y;
        c1 += ey * s0.x + e0 * s1.x;
        c2 += ez * s0.x + e0 * s1.y;
    }

    if (wid2 == 1) {
        spart[slot][lane]       = ax;
        spart[slot][32 + lane]  = ay;
        spart[slot][64 + lane]  = c0;
        spart[slot][96 + lane]  = c1;
        spart[slot][128 + lane] = c2;
    }
    __syncthreads();

    if (wid2 == 1) {
        if (lane == 0) g_cursor[node] = 0;     // reset for next launch (after sync)
        return;
    }

    ax += spart[slot][lane];
    ay += spart[slot][32 + lane];
    c0 += spart[slot][64 + lane];
    c1 += spart[slot][96 + lane];
    c2 += spart[slot][128 + lane];

    // Fused LayerNorm over 160 channels (warp 0 of the pair)
    float s = ax + ay + c0 + c1 + c2;
    #pragma unroll
    for (int o = 16; o > 0; o >>= 1) s += __shfl_xor_sync(0xFFFFFFFFu, s, o);
    float mu = s * (1.0f / 160.0f);
    float dx = ax - mu, dy = ay - mu, d0 = c0 - mu, d1 = c1 - mu, d2 = c2 - mu;
    float vs = dx * dx + dy * dy + d0 * d0 + d1 * d1 + d2 * d2;
    #pragma unroll
    for (int o = 16; o > 0; o >>= 1) vs += __shfl_xor_sync(0xFFFFFFFFu, vs, o);
    float r = rsqrtf(vs * (1.0f / 160.0f) + 1e-5f);

    float* row = out + (size_t)node * 160;
    float2 gg = ((const float2*)gamma)[lane];
    float2 bb = ((const float2*)beta)[lane];
    ((float2*)row)[lane] = make_float2(dx * r * gg.x + bb.x, dy * r * gg.y + bb.y);
    int cb = 64 + 3 * lane;
    row[cb + 0] = d0 * r * gamma[cb + 0] + beta[cb + 0];
    row[cb + 1] = d1 * r * gamma[cb + 1] + beta[cb + 1];
    row[cb + 2] = d2 * r * gamma[cb + 2] + beta[cb + 2];
}

// ---------------------------------------------------------------------------
extern "C" void kernel_launch(void* const* d_in, const int* in_sizes, int n_in,
                              void* d_out, int out_size) {
    const float* nf    = (const float*)d_in[0];
    const int*   ei    = (const int*)  d_in[1];
    const float* ea    = (const float*)d_in[2];
    const float* W0    = (const float*)d_in[4];
    const float* W1    = (const float*)d_in[5];
    const float* V0    = (const float*)d_in[8];
    const float* V1    = (const float*)d_in[9];
    const float* gamma = (const float*)d_in[10];
    const float* beta  = (const float*)d_in[11];
    float* out = (float*)d_out;

    init_scatter<<<(MB_THREADS + N_EDGES + 255) / 256, 256>>>(W0, W1, V0, V1, ei, ea);
    node_pre<<<PRE_BLOCKS, 384>>>(nf);
    gather_ln<<<N_NODES / 4, 256>>>(out, gamma, beta);
}

// round 13
// speedup vs baseline: 1.0465x; 1.0465x over previous
#include <cuda_runtime.h>
#include <cuda_fp16.h>
#include <math.h>

#define N_NODES 20000
#define N_EDGES 320000
#define CAP     96      // bucket capacity per node (Poisson(16); P(deg>=96) ~ 1e-60)

__device__ float  g_M0[96 * 64];
__device__ float  g_M1[96 * 32];
// fp16 precompute, interleaved: per node 384 halves (768B):
//   [0,256):  group c (c<64) at 4c:   {R[c], U0[c], U1[c], U2[c]}
//   [256,384): group w (w<32) at 256+4w: {P[w], Q0[w], Q1[w], Q2[w]}
__device__ __half g_preh[(size_t)N_NODES * 384];   // ~15.4 MB
__device__ int    g_cursor[N_NODES];               // zeroed by init_kernel EVERY launch
__device__ int    g_psrc[(size_t)N_NODES * CAP];
__device__ float4 g_pattr[(size_t)N_NODES * CAP];

// ---------------------------------------------------------------------------
// Kernel 1: build M0/M1 with 4-way k-split + quad shuffle reduce; zero cursors.
// ---------------------------------------------------------------------------
__global__ void init_kernel(const float* __restrict__ W0, const float* __restrict__ W1,
                            const float* __restrict__ V0, const float* __restrict__ V1) {
    int t = blockIdx.x * blockDim.x + threadIdx.x;
    if (t < 4 * 6144) {                    // M0: 6144 outputs x 4 lanes
        int out = t >> 2, l4 = t & 3;
        int u = out >> 6, c = out & 63;
        float acc = 0.f;
        int k0 = l4 * 32;
        #pragma unroll
        for (int kk = 0; kk < 32; ++kk)
            acc += W0[u * 128 + k0 + kk] * V0[(k0 + kk) * 64 + c];
        acc += __shfl_xor_sync(0xFFFFFFFFu, acc, 1);
        acc += __shfl_xor_sync(0xFFFFFFFFu, acc, 2);
        if (l4 == 0) {
            float s = 1.0f / sqrtf(96.0f * 128.0f);
            if (u >= 64) s *= 0.5773502691896258f;   // fold 1/sqrt(3)
            g_M0[out] = acc * s;
        }
    } else if (t < 4 * 9216) {             // M1: 3072 outputs x 4 lanes
        int t2 = t - 4 * 6144;
        int out = t2 >> 2, l4 = t2 & 3;
        int u = out >> 5, w = out & 31;
        float acc = 0.f;
        int k0 = l4 * 16;
        #pragma unroll
        for (int kk = 0; kk < 16; ++kk)
            acc += W1[u * 64 + k0 + kk] * V1[(k0 + kk) * 32 + w];
        acc += __shfl_xor_sync(0xFFFFFFFFu, acc, 1);
        acc += __shfl_xor_sync(0xFFFFFFFFu, acc, 2);
        if (l4 == 0) g_M1[out] = acc * (1.0f / sqrtf(96.0f * 64.0f));
    } else if (t < 4 * 9216 + N_NODES) {
        g_cursor[t - 4 * 9216] = 0;
    }
}

// ---------------------------------------------------------------------------
// accum: 4 output cols (m) x 4 nodes (f). acc[nn] += m * f[nn].
// ---------------------------------------------------------------------------
template <int ITERS>
__device__ __forceinline__ void accum4x4(const float* __restrict__ mbase, int mstride,
                                         const float* __restrict__ fbase, int fstride,
                                         float4 acc[4]) {
    #pragma unroll 8
    for (int u = 0; u < ITERS; ++u) {
        float4 m = *(const float4*)(mbase + u * mstride);
        float4 f = *(const float4*)(fbase + u * fstride);
        acc[0].x += m.x * f.x; acc[0].y += m.y * f.x; acc[0].z += m.z * f.x; acc[0].w += m.w * f.x;
        acc[1].x += m.x * f.y; acc[1].y += m.y * f.y; acc[1].z += m.z * f.y; acc[1].w += m.w * f.y;
        acc[2].x += m.x * f.z; acc[2].y += m.y * f.z; acc[2].z += m.z * f.z; acc[2].w += m.w * f.z;
        acc[3].x += m.x * f.w; acc[3].y += m.y * f.w; acc[3].z += m.z * f.w; acc[3].w += m.w * f.w;
    }
}

// ---------------------------------------------------------------------------
// Kernel 2 (fused): blocks [0,1250) = node_pre (16 nodes, register-tiled);
//                   blocks [1250,...) = scatter. Overlapped in one grid.
// ---------------------------------------------------------------------------
#define NPB 16
#define PRE_BLOCKS (N_NODES / NPB)                   // 1250
#define SC_TPB 384
#define SC_BLOCKS ((N_EDGES + SC_TPB - 1) / SC_TPB)  // 834

__global__ __launch_bounds__(384) void fused_mid(const float* __restrict__ nf,
                                                 const int* __restrict__ ei,
                                                 const float* __restrict__ ea) {
    if (blockIdx.x >= PRE_BLOCKS) {
        // ---- scatter part ----
        int e = (blockIdx.x - PRE_BLOCKS) * SC_TPB + threadIdx.x;
        if (e < N_EDGES) {
            int src = ei[e];
            int dst = ei[N_EDGES + e];
            float4 a = ((const float4*)ea)[e];
            int pos = atomicAdd(&g_cursor[dst], 1);
            if (pos < CAP) {                        // hard safety clamp: no OOB ever
                size_t idx = (size_t)dst * CAP + pos;
                g_psrc[idx]  = src;
                g_pattr[idx] = a;
            }
        }
        return;
    }

    // ---- node_pre part ----
    __shared__ float sM0[96 * 64];      // 24 KB
    __shared__ float sM1[96 * 32];      // 12 KB
    __shared__ float sfT[160 * 16];     // 10 KB: transposed features [ch][node]
    int t = threadIdx.x;
    int n0 = blockIdx.x * NPB;
    for (int i = t; i < 96 * 64; i += 384) sM0[i] = g_M0[i];
    for (int i = t; i < 96 * 32; i += 384) sM1[i] = g_M1[i];
    for (int i = t; i < 16 * 160; i += 384) {
        int n = i / 160, ch = i - n * 160;
        sfT[ch * 16 + n] = nf[(size_t)(n0 + n) * 160 + ch];
    }
    __syncthreads();

    float4 acc[4] = {{0,0,0,0},{0,0,0,0},{0,0,0,0},{0,0,0,0}};
    int g, pbase;

    if (t < 64) {                                  // R
        int h = t & 15; g = t >> 4;
        pbase = 16 * h;
        accum4x4<64>(sM0 + 4 * h, 64, sfT + 4 * g, 16, acc);
    } else if (t < 256) {                          // U_i
        int idx = t - 64;
        g = idx / 48; int r = idx % 48, i = r >> 4, cc = r & 15;
        pbase = 16 * cc + 1 + i;
        accum4x4<32>(sM0 + 64 * 64 + 4 * cc, 64, sfT + (64 + i) * 16 + 4 * g, 48, acc);
    } else if (t < 288) {                          // P
        int idx = t - 256;
        g = idx >> 3; int r = idx & 7;
        pbase = 256 + 16 * r;
        accum4x4<64>(sM1 + 4 * r, 32, sfT + 4 * g, 16, acc);
    } else {                                       // Q_i
        int idx = t - 288;
        g = idx / 24; int r = idx % 24, i = r >> 3, ww = r & 7;
        pbase = 256 + 16 * ww + 1 + i;
        accum4x4<32>(sM1 + 64 * 32 + 4 * ww, 32, sfT + (64 + i) * 16 + 4 * g, 48, acc);
    }

    size_t outb = (size_t)(n0 + 4 * g) * 384 + pbase;
    #pragma unroll
    for (int nn = 0; nn < 4; ++nn) {
        __half* o = g_preh + outb + (size_t)nn * 384;
        o[0]  = __float2half_rn(acc[nn].x);
        o[4]  = __float2half_rn(acc[nn].y);
        o[8]  = __float2half_rn(acc[nn].z);
        o[12] = __float2half_rn(acc[nn].w);
    }
}

// ---------------------------------------------------------------------------
// Kernel 3: gather + fused LayerNorm; warp per node; uniform broadcast loads.
// unroll 4 lets ptxas front-batch 4 iterations' loads (MLP~4 on the L2 chain).
// ---------------------------------------------------------------------------
__global__ __launch_bounds__(256) void gather_ln(float* __restrict__ out,
                                                 const float* __restrict__ gamma,
                                                 const float* __restrict__ beta) {
    int node = blockIdx.x * 8 + (threadIdx.x >> 5);
    int lane = threadIdx.x & 31;
    if (node >= N_NODES) return;
    int cnt = g_cursor[node];
    cnt = cnt < CAP ? cnt : CAP;            // safety clamp, mirror of scatter's
    const int*    psrc  = g_psrc  + (size_t)node * CAP;
    const float4* pattr = g_pattr + (size_t)node * CAP;

    float ax = 0.f, ay = 0.f, c0 = 0.f, c1 = 0.f, c2 = 0.f;

    #pragma unroll 4
    for (int b = 0; b < cnt; ++b) {
        int    src = __ldg(&psrc[b]);      // uniform broadcast
        float4 A   = __ldg(&pattr[b]);     // uniform broadcast
        float e0 = A.x, ex = A.y, ey = A.z, ez = A.w;
        const __half* pb = g_preh + (size_t)src * 384;
        uint4 bg = *(const uint4*)(pb + 8 * lane);        // groups 2l, 2l+1
        uint2 sm = *(const uint2*)(pb + 256 + 4 * lane);  // group l (small)
        float2 p0 = __half22float2(*(__half2*)&bg.x);     // R(2l),  U0(2l)
        float2 p1 = __half22float2(*(__half2*)&bg.y);     // U1(2l), U2(2l)
        float2 p2 = __half22float2(*(__half2*)&bg.z);     // R(2l+1),U0(2l+1)
        float2 p3 = __half22float2(*(__half2*)&bg.w);     // U1,U2 (2l+1)
        float2 s0 = __half22float2(*(__half2*)&sm.x);     // P(l), Q0(l)
        float2 s1 = __half22float2(*(__half2*)&sm.y);     // Q1(l), Q2(l)
        ax += e0 * p0.x + ex * p0.y + ey * p1.x + ez * p1.y;
        ay += e0 * p2.x + ex * p2.y + ey * p3.x + ez * p3.y;
        c0 += ex * s0.x + e0 * s0.y;
        c1 += ey * s0.x + e0 * s1.x;
        c2 += ez * s0.x + e0 * s1.y;
    }

    // Fused LayerNorm over 160 channels
    float s = ax + ay + c0 + c1 + c2;
    #pragma unroll
    for (int o = 16; o > 0; o >>= 1) s += __shfl_xor_sync(0xFFFFFFFFu, s, o);
    float mu = s * (1.0f / 160.0f);
    float dx = ax - mu, dy = ay - mu, d0 = c0 - mu, d1 = c1 - mu, d2 = c2 - mu;
    float vs = dx * dx + dy * dy + d0 * d0 + d1 * d1 + d2 * d2;
    #pragma unroll
    for (int o = 16; o > 0; o >>= 1) vs += __shfl_xor_sync(0xFFFFFFFFu, vs, o);
    float r = rsqrtf(vs * (1.0f / 160.0f) + 1e-5f);

    float* row = out + (size_t)node * 160;
    float2 gg = ((const float2*)gamma)[lane];
    float2 bb = ((const float2*)beta)[lane];
    ((float2*)row)[lane] = make_float2(dx * r * gg.x + bb.x, dy * r * gg.y + bb.y);
    int cb = 64 + 3 * lane;
    row[cb + 0] = d0 * r * gamma[cb + 0] + beta[cb + 0];
    row[cb + 1] = d1 * r * gamma[cb + 1] + beta[cb + 1];
    row[cb + 2] = d2 * r * gamma[cb + 2] + beta[cb + 2];
}

// ---------------------------------------------------------------------------
extern "C" void kernel_launch(void* const* d_in, const int* in_sizes, int n_in,
                              void* d_out, int out_size) {
    const float* nf    = (const float*)d_in[0];
    const int*   ei    = (const int*)  d_in[1];
    const float* ea    = (const float*)d_in[2];
    const float* W0    = (const float*)d_in[4];
    const float* W1    = (const float*)d_in[5];
    const float* V0    = (const float*)d_in[8];
    const float* V1    = (const float*)d_in[9];
    const float* gamma = (const float*)d_in[10];
    const float* beta  = (const float*)d_in[11];
    float* out = (float*)d_out;

    init_kernel<<<(4 * 9216 + N_NODES + 255) / 256, 256>>>(W0, W1, V0, V1);
    fused_mid<<<PRE_BLOCKS + SC_BLOCKS, 384>>>(nf, ei, ea);
    gather_ln<<<(N_NODES + 7) / 8, 256>>>(out, gamma, beta);
}

// round 15
// speedup vs baseline: 1.0952x; 1.0465x over previous
#include <cuda_runtime.h>
#include <cuda_fp16.h>
#include <math.h>

#define N_NODES 20000
#define N_EDGES 320000
#define CAP     96      // bucket capacity per node (Poisson(16); P(deg>=96) ~ 1e-60)

__device__ float  g_M0[96 * 64];
__device__ float  g_M1[96 * 32];
// fp16 precompute, interleaved: per node 384 halves (768B):
//   [0,256):  group c (c<64) at 4c:   {R[c], U0[c], U1[c], U2[c]}
//   [256,384): group w (w<32) at 256+4w: {P[w], Q0[w], Q1[w], Q2[w]}
__device__ __half g_preh[(size_t)N_NODES * 384];   // ~15.4 MB
__device__ int    g_cursor[N_NODES];               // zeroed by init_kernel EVERY launch
__device__ int    g_psrc[(size_t)N_NODES * CAP];
__device__ float4 g_pattr[(size_t)N_NODES * CAP];

// ---------------------------------------------------------------------------
// Kernel 1: build M0/M1 with 4-way k-split + quad shuffle reduce; zero cursors.
// ---------------------------------------------------------------------------
__global__ void init_kernel(const float* __restrict__ W0, const float* __restrict__ W1,
                            const float* __restrict__ V0, const float* __restrict__ V1) {
    int t = blockIdx.x * blockDim.x + threadIdx.x;
    if (t < 4 * 6144) {                    // M0: 6144 outputs x 4 lanes
        int out = t >> 2, l4 = t & 3;
        int u = out >> 6, c = out & 63;
        float acc = 0.f;
        int k0 = l4 * 32;
        #pragma unroll
        for (int kk = 0; kk < 32; ++kk)
            acc += W0[u * 128 + k0 + kk] * V0[(k0 + kk) * 64 + c];
        acc += __shfl_xor_sync(0xFFFFFFFFu, acc, 1);
        acc += __shfl_xor_sync(0xFFFFFFFFu, acc, 2);
        if (l4 == 0) {
            float s = 1.0f / sqrtf(96.0f * 128.0f);
            if (u >= 64) s *= 0.5773502691896258f;   // fold 1/sqrt(3)
            g_M0[out] = acc * s;
        }
    } else if (t < 4 * 9216) {             // M1: 3072 outputs x 4 lanes
        int t2 = t - 4 * 6144;
        int out = t2 >> 2, l4 = t2 & 3;
        int u = out >> 5, w = out & 31;
        float acc = 0.f;
        int k0 = l4 * 16;
        #pragma unroll
        for (int kk = 0; kk < 16; ++kk)
            acc += W1[u * 64 + k0 + kk] * V1[(k0 + kk) * 32 + w];
        acc += __shfl_xor_sync(0xFFFFFFFFu, acc, 1);
        acc += __shfl_xor_sync(0xFFFFFFFFu, acc, 2);
        if (l4 == 0) g_M1[out] = acc * (1.0f / sqrtf(96.0f * 64.0f));
    } else if (t < 4 * 9216 + N_NODES) {
        g_cursor[t - 4 * 9216] = 0;
    }
}

// ---------------------------------------------------------------------------
// accum: 4 output cols (m) x 4 nodes (f). acc[nn] += m * f[nn].
// ---------------------------------------------------------------------------
template <int ITERS>
__device__ __forceinline__ void accum4x4(const float* __restrict__ mbase, int mstride,
                                         const float* __restrict__ fbase, int fstride,
                                         float4 acc[4]) {
    #pragma unroll 8
    for (int u = 0; u < ITERS; ++u) {
        float4 m = *(const float4*)(mbase + u * mstride);
        float4 f = *(const float4*)(fbase + u * fstride);
        acc[0].x += m.x * f.x; acc[0].y += m.y * f.x; acc[0].z += m.z * f.x; acc[0].w += m.w * f.x;
        acc[1].x += m.x * f.y; acc[1].y += m.y * f.y; acc[1].z += m.z * f.y; acc[1].w += m.w * f.y;
        acc[2].x += m.x * f.z; acc[2].y += m.y * f.z; acc[2].z += m.z * f.z; acc[2].w += m.w * f.z;
        acc[3].x += m.x * f.w; acc[3].y += m.y * f.w; acc[3].z += m.z * f.w; acc[3].w += m.w * f.w;
    }
}

// ---------------------------------------------------------------------------
// Kernel 2 (fused, INTERLEAVED): per 5-block group, 3 node_pre + 2 scatter.
// Both roles co-resident in every wave -> scatter's latency work hides under
// node_pre's FMA work instead of serializing after it.
// ---------------------------------------------------------------------------
#define NPB 16
#define PRE_BLOCKS (N_NODES / NPB)                   // 1250
#define SC_TPB 384
#define SC_BLOCKS ((N_EDGES + SC_TPB - 1) / SC_TPB)  // 834
#define MID_BLOCKS 2085                              // ceil interleave cover

__global__ __launch_bounds__(384) void fused_mid(const float* __restrict__ nf,
                                                 const int* __restrict__ ei,
                                                 const float* __restrict__ ea) {
    int grp = blockIdx.x / 5, r = blockIdx.x % 5;
    if (r >= 3) {
        // ---- scatter role ----
        int sb = grp * 2 + (r - 3);
        if (sb >= SC_BLOCKS) return;
        int e = sb * SC_TPB + threadIdx.x;
        if (e < N_EDGES) {
            int src = ei[e];
            int dst = ei[N_EDGES + e];
            float4 a = ((const float4*)ea)[e];
            int pos = atomicAdd(&g_cursor[dst], 1);
            if (pos < CAP) {                        // hard safety clamp: no OOB ever
                size_t idx = (size_t)dst * CAP + pos;
                g_psrc[idx]  = src;
                g_pattr[idx] = a;
            }
        }
        return;
    }
    int pb = grp * 3 + r;
    if (pb >= PRE_BLOCKS) return;

    // ---- node_pre role ----
    __shared__ float sM0[96 * 64];      // 24 KB
    __shared__ float sM1[96 * 32];      // 12 KB
    __shared__ float sfT[160 * 16];     // 10 KB: transposed features [ch][node]
    int t = threadIdx.x;
    int n0 = pb * NPB;
    for (int i = t; i < 96 * 64; i += 384) sM0[i] = g_M0[i];
    for (int i = t; i < 96 * 32; i += 384) sM1[i] = g_M1[i];
    for (int i = t; i < 16 * 160; i += 384) {
        int n = i / 160, ch = i - n * 160;
        sfT[ch * 16 + n] = nf[(size_t)(n0 + n) * 160 + ch];
    }
    __syncthreads();

    float4 acc[4] = {{0,0,0,0},{0,0,0,0},{0,0,0,0},{0,0,0,0}};
    int g, pbase;

    if (t < 64) {                                  // R
        int h = t & 15; g = t >> 4;
        pbase = 16 * h;
        accum4x4<64>(sM0 + 4 * h, 64, sfT + 4 * g, 16, acc);
    } else if (t < 256) {                          // U_i
        int idx = t - 64;
        g = idx / 48; int rr = idx % 48, i = rr >> 4, cc = rr & 15;
        pbase = 16 * cc + 1 + i;
        accum4x4<32>(sM0 + 64 * 64 + 4 * cc, 64, sfT + (64 + i) * 16 + 4 * g, 48, acc);
    } else if (t < 288) {                          // P
        int idx = t - 256;
        g = idx >> 3; int rr = idx & 7;
        pbase = 256 + 16 * rr;
        accum4x4<64>(sM1 + 4 * rr, 32, sfT + 4 * g, 16, acc);
    } else {                                       // Q_i
        int idx = t - 288;
        g = idx / 24; int rr = idx % 24, i = rr >> 3, ww = rr & 7;
        pbase = 256 + 16 * ww + 1 + i;
        accum4x4<32>(sM1 + 64 * 32 + 4 * ww, 32, sfT + (64 + i) * 16 + 4 * g, 48, acc);
    }

    size_t outb = (size_t)(n0 + 4 * g) * 384 + pbase;
    #pragma unroll
    for (int nn = 0; nn < 4; ++nn) {
        __half* o = g_preh + outb + (size_t)nn * 384;
        o[0]  = __float2half_rn(acc[nn].x);
        o[4]  = __float2half_rn(acc[nn].y);
        o[8]  = __float2half_rn(acc[nn].z);
        o[12] = __float2half_rn(acc[nn].w);
    }
}

// ---------------------------------------------------------------------------
// Kernel 3: gather + fused LayerNorm; warp per node; uniform broadcast loads.
// (R9's exact loop: unroll 2 — best measured; plus cnt clamp.)
// ---------------------------------------------------------------------------
__global__ __launch_bounds__(256) void gather_ln(float* __restrict__ out,
                                                 const float* __restrict__ gamma,
                                                 const float* __restrict__ beta) {
    int node = blockIdx.x * 8 + (threadIdx.x >> 5);
    int lane = threadIdx.x & 31;
    if (node >= N_NODES) return;
    int cnt = g_cursor[node];
    cnt = cnt < CAP ? cnt : CAP;            // safety clamp, mirror of scatter's
    const int*    psrc  = g_psrc  + (size_t)node * CAP;
    const float4* pattr = g_pattr + (size_t)node * CAP;

    float ax = 0.f, ay = 0.f, c0 = 0.f, c1 = 0.f, c2 = 0.f;

    #pragma unroll 2
    for (int b = 0; b < cnt; ++b) {
        int    src = __ldg(&psrc[b]);      // uniform broadcast
        float4 A   = __ldg(&pattr[b]);     // uniform broadcast
        float e0 = A.x, ex = A.y, ey = A.z, ez = A.w;
        const __half* pb = g_preh + (size_t)src * 384;
        uint4 bg = *(const uint4*)(pb + 8 * lane);        // groups 2l, 2l+1
        uint2 sm = *(const uint2*)(pb + 256 + 4 * lane);  // group l (small)
        float2 p0 = __half22float2(*(__half2*)&bg.x);     // R(2l),  U0(2l)
        float2 p1 = __half22float2(*(__half2*)&bg.y);     // U1(2l), U2(2l)
        float2 p2 = __half22float2(*(__half2*)&bg.z);     // R(2l+1),U0(2l+1)
        float2 p3 = __half22float2(*(__half2*)&bg.w);     // U1,U2 (2l+1)
        float2 s0 = __half22float2(*(__half2*)&sm.x);     // P(l), Q0(l)
        float2 s1 = __half22float2(*(__half2*)&sm.y);     // Q1(l), Q2(l)
        ax += e0 * p0.x + ex * p0.y + ey * p1.x + ez * p1.y;
        ay += e0 * p2.x + ex * p2.y + ey * p3.x + ez * p3.y;
        c0 += ex * s0.x + e0 * s0.y;
        c1 += ey * s0.x + e0 * s1.x;
        c2 += ez * s0.x + e0 * s1.y;
    }

    // Fused LayerNorm over 160 channels
    float s = ax + ay + c0 + c1 + c2;
    #pragma unroll
    for (int o = 16; o > 0; o >>= 1) s += __shfl_xor_sync(0xFFFFFFFFu, s, o);
    float mu = s * (1.0f / 160.0f);
    float dx = ax - mu, dy = ay - mu, d0 = c0 - mu, d1 = c1 - mu, d2 = c2 - mu;
    float vs = dx * dx + dy * dy + d0 * d0 + d1 * d1 + d2 * d2;
    #pragma unroll
    for (int o = 16; o > 0; o >>= 1) vs += __shfl_xor_sync(0xFFFFFFFFu, vs, o);
    float r = rsqrtf(vs * (1.0f / 160.0f) + 1e-5f);

    float* row = out + (size_t)node * 160;
    float2 gg = ((const float2*)gamma)[lane];
    float2 bb = ((const float2*)beta)[lane];
    ((float2*)row)[lane] = make_float2(dx * r * gg.x + bb.x, dy * r * gg.y + bb.y);
    int cb = 64 + 3 * lane;
    row[cb + 0] = d0 * r * gamma[cb + 0] + beta[cb + 0];
    row[cb + 1] = d1 * r * gamma[cb + 1] + beta[cb + 1];
    row[cb + 2] = d2 * r * gamma[cb + 2] + beta[cb + 2];
}

// ---------------------------------------------------------------------------
extern "C" void kernel_launch(void* const* d_in, const int* in_sizes, int n_in,
                              void* d_out, int out_size) {
    const float* nf    = (const float*)d_in[0];
    const int*   ei    = (const int*)  d_in[1];
    const float* ea    = (const float*)d_in[2];
    const float* W0    = (const float*)d_in[4];
    const float* W1    = (const float*)d_in[5];
    const float* V0    = (const float*)d_in[8];
    const float* V1    = (const float*)d_in[9];
    const float* gamma = (const float*)d_in[10];
    const float* beta  = (const float*)d_in[11];
    float* out = (float*)d_out;

    init_kernel<<<(4 * 9216 + N_NODES + 255) / 256, 256>>>(W0, W1, V0, V1);
    fused_mid<<<MID_BLOCKS, 384>>>(nf, ei, ea);
    gather_ln<<<(N_NODES + 7) / 8, 256>>>(out, gamma, beta);
}